// round 5
// baseline (speedup 1.0000x reference)
#include <cuda_runtime.h>
#include <cstdint>

// MultiNetwork: 32 independent MLPs 256->512->512->128 (relu, relu, id), batch 4096.
// Fused mma.sync tf32 kernel (harness PTX target is plain sm_103 -> no tcgen05).
// One CTA per (net, 128-row batch tile); CTA tile 128x128, warp tile 32x64.
// All MMA operands rounded with cvt.rna.tf32 to remove truncation bias.

#define DINLINE __device__ __forceinline__

static constexpr int NETS  = 32;
static constexpr int BATCH = 4096;
static constexpr int D_IN  = 256;
static constexpr int D_H   = 512;
static constexpr int D_OUT = 128;

static constexpr int MT = 128;   // CTA batch tile (M)
static constexpr int NC = 128;   // CTA output tile (N)
static constexpr int KC = 32;    // K chunk
static constexpr int LD = 36;    // padded smem row stride in floats (conflict-free)

static constexpr int A_ST = MT * LD;                   // floats per A stage (4608)
static constexpr int B_ST = NC * LD;                   // floats per B stage (4608)
static constexpr int SMEM_BYTES = (2 * A_ST + 2 * B_ST) * 4;   // 73728

// Inter-layer activation scratch (written/read by the same CTA).
__device__ float g_h1[(size_t)NETS * BATCH * D_H];   // 256 MB
__device__ float g_h2[(size_t)NETS * BATCH * D_H];   // 256 MB

DINLINE uint32_t tf32r(float x) {
    uint32_t u;
    asm("cvt.rna.tf32.f32 %0, %1;" : "=r"(u) : "f"(x));
    return u;
}

DINLINE void mma8(float* d, const uint32_t* a, const uint32_t* b) {
    asm volatile(
        "mma.sync.aligned.m16n8k8.row.col.f32.tf32.tf32.f32 "
        "{%0,%1,%2,%3}, {%4,%5,%6,%7}, {%8,%9}, {%0,%1,%2,%3};"
        : "+f"(d[0]), "+f"(d[1]), "+f"(d[2]), "+f"(d[3])
        : "r"(a[0]), "r"(a[1]), "r"(a[2]), "r"(a[3]), "r"(b[0]), "r"(b[1]));
}

__global__ void __launch_bounds__(256)
multinet_mma(const float* __restrict__ x,
             const float* __restrict__ W1, const float* __restrict__ b1,
             const float* __restrict__ W2, const float* __restrict__ b2,
             const float* __restrict__ W3, const float* __restrict__ b3,
             float* __restrict__ out)
{
    extern __shared__ uint32_t sm[];
    uint32_t* Abuf = sm;              // 2 stages of [MT x KC] (padded)
    uint32_t* Bbuf = sm + 2 * A_ST;   // 2 stages of [NC x KC] (padded)

    const int tid  = threadIdx.x;
    const int lane = tid & 31, wid = tid >> 5;
    const int gid  = lane >> 2, tig = lane & 3;     // mma quad indices
    const int warpM = wid >> 1, warpN = wid & 1;    // 4 x 2 warp grid
    const int mtile = blockIdx.x, g = blockIdx.y;
    const int m0    = mtile * MT;

    float* hseg1 = g_h1 + ((size_t)g * BATCH + m0) * D_H;
    float* hseg2 = g_h2 + ((size_t)g * BATCH + m0) * D_H;

    for (int l = 0; l < 3; l++) {
        const float *Asrc, *Wl, *bl;
        int Ast, K, Nl;
        float* hdst;
        bool isout;
        if (l == 0) {
            Asrc = x + (size_t)m0 * D_IN; Ast = D_IN; K = D_IN; Nl = D_H;
            Wl = W1; bl = b1; hdst = hseg1; isout = false;
        } else if (l == 1) {
            Asrc = hseg1; Ast = D_H; K = D_H; Nl = D_H;
            Wl = W2; bl = b2; hdst = hseg2; isout = false;
        } else {
            Asrc = hseg2; Ast = D_H; K = D_H; Nl = D_OUT;
            Wl = W3; bl = b3; hdst = nullptr; isout = true;
        }
        const int nk = K / KC;

        for (int n0 = 0; n0 < Nl; n0 += NC) {
            const float* Bsrc = Wl + ((size_t)g * Nl + n0) * K;

            float acc[2][8][4];
            #pragma unroll
            for (int i = 0; i < 2; i++)
                #pragma unroll
                for (int j = 0; j < 8; j++)
                    #pragma unroll
                    for (int q = 0; q < 4; q++) acc[i][j][q] = 0.0f;

            float4 ar[4], br[4];   // LDG staging (held across compute)

            auto ldg_chunk = [&](int kk) {
                const float* ap = Asrc + kk * KC;
                const float* bp = Bsrc + kk * KC;
                #pragma unroll
                for (int i = 0; i < 4; i++) {
                    int f = tid + i * 256;
                    int r = f >> 3, c = f & 7;
                    ar[i] = *reinterpret_cast<const float4*>(ap + (size_t)r * Ast + c * 4);
                    br[i] = *reinterpret_cast<const float4*>(bp + (size_t)r * K   + c * 4);
                }
            };
            auto sts_chunk = [&](int s) {
                uint32_t* Ad = Abuf + s * A_ST;
                uint32_t* Bd = Bbuf + s * B_ST;
                #pragma unroll
                for (int i = 0; i < 4; i++) {
                    int f = tid + i * 256;
                    int r = f >> 3, c = f & 7;
                    uint4 va = make_uint4(tf32r(ar[i].x), tf32r(ar[i].y),
                                          tf32r(ar[i].z), tf32r(ar[i].w));
                    uint4 vb = make_uint4(tf32r(br[i].x), tf32r(br[i].y),
                                          tf32r(br[i].z), tf32r(br[i].w));
                    *reinterpret_cast<uint4*>(Ad + r * LD + c * 4) = va;
                    *reinterpret_cast<uint4*>(Bd + r * LD + c * 4) = vb;
                }
            };
            auto compute = [&](int s) {
                const uint32_t* A = Abuf + s * A_ST;
                const uint32_t* B = Bbuf + s * B_ST;
                #pragma unroll
                for (int ks = 0; ks < 4; ks++) {
                    const int k0 = ks * 8;
                    uint32_t a[2][4];
                    #pragma unroll
                    for (int mf = 0; mf < 2; mf++) {
                        int rb = warpM * 32 + mf * 16;
                        const uint32_t* Ar = A + k0 + tig;
                        a[mf][0] = Ar[(rb + gid)     * LD];
                        a[mf][1] = Ar[(rb + gid + 8) * LD];
                        a[mf][2] = Ar[(rb + gid)     * LD + 4];
                        a[mf][3] = Ar[(rb + gid + 8) * LD + 4];
                    }
                    #pragma unroll
                    for (int nf = 0; nf < 8; nf++) {
                        int nb = warpN * 64 + nf * 8 + gid;
                        uint32_t b[2];
                        b[0] = B[nb * LD + k0 + tig];
                        b[1] = B[nb * LD + k0 + tig + 4];
                        mma8(acc[0][nf], a[0], b);
                        mma8(acc[1][nf], a[1], b);
                    }
                }
            };

            // double-buffered K pipeline
            ldg_chunk(0);
            sts_chunk(0);
            __syncthreads();
            for (int kk = 0; kk < nk; kk++) {
                if (kk + 1 < nk) ldg_chunk(kk + 1);   // overlap LDG with compute
                compute(kk & 1);
                __syncthreads();                       // all reads of other stage done
                if (kk + 1 < nk) {
                    sts_chunk((kk + 1) & 1);
                    __syncthreads();
                }
            }

            // epilogue: +bias, relu (hidden), store
            #pragma unroll
            for (int mf = 0; mf < 2; mf++) {
                #pragma unroll
                for (int nf = 0; nf < 8; nf++) {
                    int col = n0 + warpN * 64 + nf * 8 + tig * 2;
                    float bb0 = __ldg(bl + (size_t)g * Nl + col);
                    float bb1 = __ldg(bl + (size_t)g * Nl + col + 1);
                    int r0 = warpM * 32 + mf * 16 + gid;
                    float v00 = acc[mf][nf][0] + bb0, v01 = acc[mf][nf][1] + bb1;
                    float v10 = acc[mf][nf][2] + bb0, v11 = acc[mf][nf][3] + bb1;
                    if (!isout) {
                        v00 = fmaxf(v00, 0.0f); v01 = fmaxf(v01, 0.0f);
                        v10 = fmaxf(v10, 0.0f); v11 = fmaxf(v11, 0.0f);
                        *reinterpret_cast<float2*>(hdst + (size_t)r0 * D_H + col) =
                            make_float2(v00, v01);
                        *reinterpret_cast<float2*>(hdst + (size_t)(r0 + 8) * D_H + col) =
                            make_float2(v10, v11);
                    } else {
                        float* o = out + (size_t)(m0 + r0) * (NETS * D_OUT)
                                 + g * D_OUT + col;   // n0 == 0 for layer 3
                        *reinterpret_cast<float2*>(o) = make_float2(v00, v01);
                        *reinterpret_cast<float2*>(o + 8 * (NETS * D_OUT)) =
                            make_float2(v10, v11);
                    }
                }
            }
            __syncthreads();   // h visible to whole CTA before next layer / n-chunk
        }
    }
}

extern "C" void kernel_launch(void* const* d_in, const int* in_sizes, int n_in,
                              void* d_out, int out_size)
{
    const float* x  = (const float*)d_in[0];
    const float* W1 = (const float*)d_in[1];
    const float* b1 = (const float*)d_in[2];
    const float* W2 = (const float*)d_in[3];
    const float* b2 = (const float*)d_in[4];
    const float* W3 = (const float*)d_in[5];
    const float* b3 = (const float*)d_in[6];
    float* out = (float*)d_out;

    cudaFuncSetAttribute(multinet_mma,
                         cudaFuncAttributeMaxDynamicSharedMemorySize, SMEM_BYTES);

    dim3 grid(BATCH / MT, NETS);   // 32 batch tiles x 32 nets
    multinet_mma<<<grid, 256, SMEM_BYTES>>>(x, W1, b1, W2, b2, W3, b3, out);
}

// round 7
// speedup vs baseline: 1.0699x; 1.0699x over previous
#include <cuda_runtime.h>
#include <cstdint>

// MultiNetwork: 32 MLPs 256->512->512->128 (relu, relu, id), batch 4096.
// Round 6: mma.sync tf32, CTA 128x256, 8 warps of 64x64, ldmatrix fragments,
// cp.async.cg weight streaming, pre-rounded operands, 3-stage single-sync pipe.

#define DINLINE __device__ __forceinline__

static constexpr int NETS  = 32;
static constexpr int BATCH = 4096;
static constexpr int D_IN  = 256;
static constexpr int D_H   = 512;
static constexpr int D_OUT = 128;

static constexpr int MT  = 128;   // CTA batch tile
static constexpr int KC  = 32;    // K chunk
static constexpr int LD  = 36;    // padded smem row stride (floats)

static constexpr int A_F = MT * LD;            // 4608 floats
static constexpr int B_F = 256 * LD;           // 9216 floats (max Nc=256)
static constexpr int A_BYTES   = A_F * 4;      // 18432
static constexpr int STAGE_F   = A_F + B_F;    // 13824
static constexpr int STAGE_BYTES = STAGE_F * 4;     // 55296
static constexpr int SMEM_BYTES  = 3 * STAGE_BYTES; // 165888

// Pre-rounded operands + inter-layer activations.
__device__ float g_xr [(size_t)BATCH * D_IN];
__device__ float g_w1r[(size_t)NETS * D_H  * D_IN];
__device__ float g_w2r[(size_t)NETS * D_H  * D_H];
__device__ float g_w3r[(size_t)NETS * D_OUT * D_H];
__device__ float g_h1 [(size_t)NETS * BATCH * D_H];
__device__ float g_h2 [(size_t)NETS * BATCH * D_H];

DINLINE uint32_t smem_u32(const void* p) {
    uint32_t a;
    asm("{ .reg .u64 t; cvta.to.shared.u64 t, %1; cvt.u32.u64 %0, t; }" : "=r"(a) : "l"(p));
    return a;
}
DINLINE uint32_t tf32r(float x) {
    uint32_t u;
    asm("cvt.rna.tf32.f32 %0, %1;" : "=r"(u) : "f"(x));
    return u;
}
DINLINE void cpasync16(uint32_t dst, const void* src) {
    asm volatile("cp.async.cg.shared.global [%0], [%1], 16;"
                 :: "r"(dst), "l"(src) : "memory");
}
DINLINE void cp_commit() { asm volatile("cp.async.commit_group;" ::: "memory"); }
DINLINE void cp_wait1()  { asm volatile("cp.async.wait_group 1;" ::: "memory"); }

DINLINE void ldsm4(uint32_t* r, uint32_t addr) {
    asm volatile("ldmatrix.sync.aligned.m8n8.x4.shared.b16 {%0,%1,%2,%3}, [%4];"
                 : "=r"(r[0]), "=r"(r[1]), "=r"(r[2]), "=r"(r[3]) : "r"(addr));
}
DINLINE void mma8(float* d, const uint32_t* a, const uint32_t* b) {
    asm volatile(
        "mma.sync.aligned.m16n8k8.row.col.f32.tf32.tf32.f32 "
        "{%0,%1,%2,%3}, {%4,%5,%6,%7}, {%8,%9}, {%0,%1,%2,%3};"
        : "+f"(d[0]), "+f"(d[1]), "+f"(d[2]), "+f"(d[3])
        : "r"(a[0]), "r"(a[1]), "r"(a[2]), "r"(a[3]), "r"(b[0]), "r"(b[1]));
}

// One GEMM segment: C[128, NF*32] = A[128,K] * B^T, +bias (+relu for hidden).
// NF = n-fragments per warp (8 -> Nc=256, 4 -> Nc=128).
template<int NF, bool ISOUT>
DINLINE void run_segment(const float* __restrict__ Asrc, int As, int K,
                         const float* __restrict__ Bsrc,
                         const float* __restrict__ bias,
                         float* __restrict__ dst, int dstride)
{
    extern __shared__ float smf[];
    const uint32_t sb = smem_u32(smf);
    const int tid  = threadIdx.x;
    const int lane = tid & 31, wid = tid >> 5;
    const int gid  = lane >> 2, tig = lane & 3;
    const int wm   = wid & 1, wn = wid >> 1;     // 2 x 4 warps of 64 x (NF*8)

    const int nk = K / KC;
    float acc[4][NF][4];
    #pragma unroll
    for (int i = 0; i < 4; i++)
        #pragma unroll
        for (int j = 0; j < NF; j++)
            #pragma unroll
            for (int q = 0; q < 4; q++) acc[i][j][q] = 0.0f;

    float4 av[4];   // A staging (LDG -> STS)

    auto ldgA = [&](int kk) {
        #pragma unroll
        for (int i = 0; i < 4; i++) {
            int f = tid + i * 256, r = f >> 3, c = f & 7;
            av[i] = *reinterpret_cast<const float4*>(
                Asrc + (size_t)r * As + kk * KC + c * 4);
        }
    };
    auto stsA = [&](int st) {
        #pragma unroll
        for (int i = 0; i < 4; i++) {
            int f = tid + i * 256, r = f >> 3, c = f & 7;
            *reinterpret_cast<float4*>(smf + st * STAGE_F + r * LD + c * 4) = av[i];
        }
    };
    auto issueB = [&](int kk, int st) {
        uint32_t bb = sb + st * STAGE_BYTES + A_BYTES;
        #pragma unroll
        for (int i = 0; i < NF; i++) {
            int f = tid + i * 256, r = f >> 3, c = f & 7;
            cpasync16(bb + (uint32_t)(r * LD + c * 4) * 4,
                      Bsrc + (size_t)r * K + kk * KC + c * 4);
        }
    };

    // per-lane ldmatrix offsets (bytes)
    const uint32_t aoff = (uint32_t)(((lane & 15) * LD + ((lane >> 4) & 1) * 4) * 4);
    const uint32_t boff = (uint32_t)(((((lane >> 4) & 1) * 8 + (lane & 7)) * LD
                                      + ((lane >> 3) & 1) * 4) * 4);

    auto compute = [&](int st) {
        const uint32_t Ab = sb + st * STAGE_BYTES + (uint32_t)(wm * 64 * LD * 4) + aoff;
        const uint32_t Bb = sb + st * STAGE_BYTES + A_BYTES
                          + (uint32_t)(wn * NF * 8 * LD * 4) + boff;
        #pragma unroll
        for (int ks = 0; ks < 4; ks++) {
            const uint32_t k0b = (uint32_t)(ks * 32);
            uint32_t a[4][4];
            #pragma unroll
            for (int mf = 0; mf < 4; mf++)
                ldsm4(a[mf], Ab + (uint32_t)(mf * 16 * LD * 4) + k0b);
            #pragma unroll
            for (int p = 0; p < NF / 2; p++) {
                uint32_t bt[4];
                ldsm4(bt, Bb + (uint32_t)(p * 16 * LD * 4) + k0b);
                #pragma unroll
                for (int mf = 0; mf < 4; mf++) {
                    mma8(acc[mf][2 * p],     a[mf], bt);
                    mma8(acc[mf][2 * p + 1], a[mf], bt + 2);
                }
            }
        }
    };

    // ---- 3-stage pipeline, one __syncthreads per chunk ----
    ldgA(0); stsA(0); issueB(0, 0); cp_commit();
    ldgA(1); stsA(1); issueB(1, 1); cp_commit();

    int st = 0, st2 = 2;
    for (int kk = 0; kk < nk; kk++) {
        cp_wait1();
        __syncthreads();
        const bool more = (kk + 2 < nk);
        if (more) { ldgA(kk + 2); issueB(kk + 2, st2); }
        cp_commit();
        compute(st);
        if (more) stsA(st2);
        st  = (st  == 2) ? 0 : st  + 1;
        st2 = (st2 == 2) ? 0 : st2 + 1;
    }

    // ---- epilogue ----
    #pragma unroll
    for (int mf = 0; mf < 4; mf++) {
        #pragma unroll
        for (int nf = 0; nf < NF; nf++) {
            const int rr  = wm * 64 + mf * 16 + gid;
            const int col = wn * NF * 8 + nf * 8 + tig * 2;
            const float b0 = __ldg(bias + col), b1 = __ldg(bias + col + 1);
            float v00 = acc[mf][nf][0] + b0, v01 = acc[mf][nf][1] + b1;
            float v10 = acc[mf][nf][2] + b0, v11 = acc[mf][nf][3] + b1;
            if (!ISOUT) {
                v00 = fmaxf(v00, 0.0f); v01 = fmaxf(v01, 0.0f);
                v10 = fmaxf(v10, 0.0f); v11 = fmaxf(v11, 0.0f);
                // pre-round next layer's operand
                float2 lo = make_float2(__uint_as_float(tf32r(v00)),
                                        __uint_as_float(tf32r(v01)));
                float2 hi = make_float2(__uint_as_float(tf32r(v10)),
                                        __uint_as_float(tf32r(v11)));
                *reinterpret_cast<float2*>(dst + (size_t)rr * dstride + col) = lo;
                *reinterpret_cast<float2*>(dst + (size_t)(rr + 8) * dstride + col) = hi;
            } else {
                *reinterpret_cast<float2*>(dst + (size_t)rr * dstride + col) =
                    make_float2(v00, v01);
                *reinterpret_cast<float2*>(dst + (size_t)(rr + 8) * dstride + col) =
                    make_float2(v10, v11);
            }
        }
    }
    if (!ISOUT) asm volatile("membar.gl;" ::: "memory");  // h -> next cp.async
    __syncthreads();   // smem + h safe for next segment
}

__global__ void __launch_bounds__(256, 1)
multinet6(const float* __restrict__ b1, const float* __restrict__ b2,
          const float* __restrict__ b3, float* __restrict__ out)
{
    const int m0 = blockIdx.x * MT;
    const int g  = blockIdx.y;

    float* h1 = g_h1 + ((size_t)g * BATCH + m0) * D_H;
    float* h2 = g_h2 + ((size_t)g * BATCH + m0) * D_H;

    // layer 1: [128,256] x W1^T -> [128,512] in two 256-wide segments
    run_segment<8, false>(g_xr + (size_t)m0 * D_IN, D_IN, D_IN,
                          g_w1r + (size_t)g * D_H * D_IN,
                          b1 + (size_t)g * D_H, h1, D_H);
    run_segment<8, false>(g_xr + (size_t)m0 * D_IN, D_IN, D_IN,
                          g_w1r + ((size_t)g * D_H + 256) * D_IN,
                          b1 + (size_t)g * D_H + 256, h1 + 256, D_H);
    // layer 2
    run_segment<8, false>(h1, D_H, D_H,
                          g_w2r + (size_t)g * D_H * D_H,
                          b2 + (size_t)g * D_H, h2, D_H);
    run_segment<8, false>(h1, D_H, D_H,
                          g_w2r + ((size_t)g * D_H + 256) * D_H,
                          b2 + (size_t)g * D_H + 256, h2 + 256, D_H);
    // layer 3 (identity, Nc=128)
    run_segment<4, true>(h2, D_H, D_H,
                         g_w3r + (size_t)g * D_OUT * D_H,
                         b3 + (size_t)g * D_OUT,
                         out + (size_t)m0 * (NETS * D_OUT) + g * D_OUT,
                         NETS * D_OUT);
}

// Pre-round fp32 -> tf32 (rna) into scratch.
__global__ void round_k(const float4* __restrict__ in, float4* __restrict__ o, int n4)
{
    int i = blockIdx.x * blockDim.x + threadIdx.x;
    if (i < n4) {
        float4 v = in[i];
        o[i] = make_float4(__uint_as_float(tf32r(v.x)), __uint_as_float(tf32r(v.y)),
                           __uint_as_float(tf32r(v.z)), __uint_as_float(tf32r(v.w)));
    }
}

extern "C" void kernel_launch(void* const* d_in, const int* in_sizes, int n_in,
                              void* d_out, int out_size)
{
    const float* x  = (const float*)d_in[0];
    const float* W1 = (const float*)d_in[1];
    const float* b1 = (const float*)d_in[2];
    const float* W2 = (const float*)d_in[3];
    const float* b2 = (const float*)d_in[4];
    const float* W3 = (const float*)d_in[5];
    const float* b3 = (const float*)d_in[6];
    float* out = (float*)d_out;

    void *pxr, *pw1, *pw2, *pw3;
    cudaGetSymbolAddress(&pxr, g_xr);
    cudaGetSymbolAddress(&pw1, g_w1r);
    cudaGetSymbolAddress(&pw2, g_w2r);
    cudaGetSymbolAddress(&pw3, g_w3r);

    auto launch_round = [&](const float* src, void* dst, size_t n) {
        int n4 = (int)(n / 4);
        round_k<<<(n4 + 255) / 256, 256>>>((const float4*)src, (float4*)dst, n4);
    };
    launch_round(x,  pxr, (size_t)BATCH * D_IN);
    launch_round(W1, pw1, (size_t)NETS * D_H * D_IN);
    launch_round(W2, pw2, (size_t)NETS * D_H * D_H);
    launch_round(W3, pw3, (size_t)NETS * D_OUT * D_H);

    cudaFuncSetAttribute(multinet6,
                         cudaFuncAttributeMaxDynamicSharedMemorySize, SMEM_BYTES);
    dim3 grid(BATCH / MT, NETS);   // 32 x 32 = 1024 CTAs
    multinet6<<<grid, 256, SMEM_BYTES>>>(b1, b2, b3, out);
}